// round 6
// baseline (speedup 1.0000x reference)
#include <cuda_runtime.h>
#include <cuda_bf16.h>

// Problem constants
#define S_LEN  2048
#define DMODEL 4096
#define NH     32
#define NHK    8
#define HD     128
#define TCACHE 2048

// ---------------------------------------------------------------------------
// Scratch (allocation-free: __device__ globals)
// ---------------------------------------------------------------------------
__device__ float g_q [S_LEN * DMODEL];
__device__ float g_k [S_LEN * NHK * HD];
__device__ float g_v [S_LEN * NHK * HD];
__device__ float g_ao[S_LEN * DMODEL];

// ---------------------------------------------------------------------------
// Helpers
// ---------------------------------------------------------------------------
__device__ __forceinline__ unsigned f2tf(float f) {
  unsigned u;
  asm("cvt.rn.tf32.f32 %0, %1;" : "=r"(u) : "f"(f));
  return u;
}
__device__ __forceinline__ unsigned smem_u32(const void* p) {
  unsigned a;
  asm("{ .reg .u64 t; cvta.to.shared.u64 t, %1; cvt.u32.u64 %0, t; }"
      : "=r"(a) : "l"(p));
  return a;
}
__device__ __forceinline__ void cp16(unsigned dst, const void* src) {
  asm volatile("cp.async.cg.shared.global [%0], [%1], 16;"
               :: "r"(dst), "l"(src));
}
__device__ __forceinline__ void mma_tf32(float* c, const unsigned* a,
                                         const unsigned* b) {
  asm volatile(
    "mma.sync.aligned.m16n8k8.row.col.f32.tf32.tf32.f32 "
    "{%0,%1,%2,%3}, {%4,%5,%6,%7}, {%8,%9}, {%0,%1,%2,%3};"
    : "+f"(c[0]), "+f"(c[1]), "+f"(c[2]), "+f"(c[3])
    : "r"(a[0]), "r"(a[1]), "r"(a[2]), "r"(a[3]), "r"(b[0]), "r"(b[1]));
}

// ---------------------------------------------------------------------------
// Tensor-core GEMM body, 3-stage cp.async pipeline, one sync per k-iter.
// C[M,N] = A[M,K] @ B[K,N]; As stride 36, Bs stride 136 (conflict-free).
// ---------------------------------------------------------------------------
#define ASTRIDE 36
#define BSTRIDE 136
#define ABUF (128 * ASTRIDE)
#define BBUF (32 * BSTRIDE)
#define GEMM_SMEM ((3 * ABUF + 3 * BBUF) * 4)   // 107520 bytes

__device__ __forceinline__
void gemm_body(const float* __restrict__ A, const float* __restrict__ Bw,
               float* __restrict__ C, int N, int K,
               const float* __restrict__ rope, int bm, int bn, float* gsm) {
  float* AsB = gsm;                 // [3][128][36]
  float* BsB = gsm + 3 * ABUF;      // [3][32][136]
  int tid  = threadIdx.x;
  int wid  = tid >> 5, lane = tid & 31;
  int wm   = (wid >> 2) * 64;
  int wn   = (wid & 3) * 32;
  int gr   = lane >> 2;
  int tg   = lane & 3;

  int arow = tid >> 1, acol = (tid & 1) * 16;
  int brow = tid >> 3, bcol = (tid & 7) * 16;

  auto issue_copy = [&](int k0, int buf) {
    unsigned adst = smem_u32(AsB + buf * ABUF + arow * ASTRIDE + acol);
    const float* asrc = A + (size_t)(bm + arow) * K + k0 + acol;
    #pragma unroll
    for (int i = 0; i < 4; i++) cp16(adst + 16 * i, asrc + 4 * i);
    unsigned bdst = smem_u32(BsB + buf * BBUF + brow * BSTRIDE + bcol);
    const float* bsrc = Bw + (size_t)(k0 + brow) * N + bn + bcol;
    #pragma unroll
    for (int i = 0; i < 4; i++) cp16(bdst + 16 * i, bsrc + 4 * i);
    asm volatile("cp.async.commit_group;" ::: "memory");
  };

  float acc[4][4][4] = {};
  int nit = K / 32;
  issue_copy(0, 0);
  issue_copy(32, 1);

  int buf = 0;
  for (int it = 0; it < nit; it++) {
    if (it < nit - 1)
      asm volatile("cp.async.wait_group 1;" ::: "memory");
    else
      asm volatile("cp.async.wait_group 0;" ::: "memory");
    __syncthreads();
    if (it + 2 < nit) issue_copy((it + 2) * 32, (it + 2) % 3);

    const float* Ab = AsB + buf * ABUF;
    const float* Bb = BsB + buf * BBUF;
    #pragma unroll
    for (int kk = 0; kk < 32; kk += 8) {
      unsigned af[4][4], bf[4][2];
      #pragma unroll
      for (int mt = 0; mt < 4; mt++) {
        int m0 = wm + mt * 16;
        af[mt][0] = f2tf(Ab[(m0 + gr    ) * ASTRIDE + kk + tg    ]);
        af[mt][1] = f2tf(Ab[(m0 + 8 + gr) * ASTRIDE + kk + tg    ]);
        af[mt][2] = f2tf(Ab[(m0 + gr    ) * ASTRIDE + kk + 4 + tg]);
        af[mt][3] = f2tf(Ab[(m0 + 8 + gr) * ASTRIDE + kk + 4 + tg]);
      }
      #pragma unroll
      for (int nt = 0; nt < 4; nt++) {
        bf[nt][0] = f2tf(Bb[(kk + tg    ) * BSTRIDE + wn + nt * 8 + gr]);
        bf[nt][1] = f2tf(Bb[(kk + 4 + tg) * BSTRIDE + wn + nt * 8 + gr]);
      }
      #pragma unroll
      for (int mt = 0; mt < 4; mt++)
        #pragma unroll
        for (int nt = 0; nt < 4; nt++)
          mma_tf32(acc[mt][nt], af[mt], bf[nt]);
    }
    buf = (buf + 1) % 3;
  }

  #pragma unroll
  for (int mt = 0; mt < 4; mt++) {
    #pragma unroll
    for (int half = 0; half < 2; half++) {
      int m = bm + wm + mt * 16 + gr + half * 8;
      const float* rp = rope ? (rope + (size_t)m * HD) : (const float*)0;
      #pragma unroll
      for (int nt = 0; nt < 4; nt++) {
        int n = bn + wn + nt * 8 + 2 * tg;
        float x = acc[mt][nt][half * 2 + 0];
        float y = acc[mt][nt][half * 2 + 1];
        if (rp) {
          x *= rp[n & (HD - 1)];
          y *= rp[(n + 1) & (HD - 1)];
        }
        float2 v; v.x = x; v.y = y;
        *(float2*)&C[(size_t)m * N + n] = v;
      }
    }
  }
}

// Fused QKV projection: z selects {wq->q, wk->k, wv->v}
__global__ __launch_bounds__(256, 2)
void gemm_qkv(const float* __restrict__ x,
              const float* __restrict__ wq, const float* __restrict__ wk,
              const float* __restrict__ wv,
              float* __restrict__ q, float* __restrict__ k,
              float* __restrict__ v, const float* __restrict__ rope) {
  extern __shared__ float gsm[];
  int z = blockIdx.z;
  const float* B = (z == 0) ? wq : (z == 1) ? wk : wv;
  float* C       = (z == 0) ? g_q ? q : q : (z == 1) ? k : v;
  int N          = (z == 0) ? DMODEL : NHK * HD;
  if (blockIdx.x * 128 >= N) return;
  const float* rp = (z == 2) ? (const float*)0 : rope;
  gemm_body(x, B, C, N, DMODEL, rp, blockIdx.y * 128, blockIdx.x * 128, gsm);
}

// Plain GEMM (output projection)
__global__ __launch_bounds__(256, 2)
void gemm_mma(const float* __restrict__ A, const float* __restrict__ Bw,
              float* __restrict__ C, int N, int K,
              const float* __restrict__ rope) {
  extern __shared__ float gsm[];
  gemm_body(A, Bw, C, N, K, rope, blockIdx.y * 128, blockIdx.x * 128, gsm);
}

// ---------------------------------------------------------------------------
// Tensor-core flash attention (tf32 mma), 512 threads (16 warps).
// BQ=128, BKV=64. Warp (wq 0..7, wn 0..1): S tile 16q x 32t, PV 16q x 64d.
// Smem (words): Qs[128][132]@0  Ks[2][128][68]@16896  Vs[128][68]@34304
//   P[128][68]@43008  m/l/al[128]@51712+  smax/ssum[2][128]@52096+
// ---------------------------------------------------------------------------
#define BQ  128
#define BKV 64
#define AQS 0
#define AKS 16896
#define AVS 34304
#define APS 43008
#define AMS 51712
#define ALS 51840
#define AAS 51968
#define ASX 52096
#define ASS 52352
#define ATTN_SMEM_BYTES (52608 * 4)
#define ATH 512

__global__ __launch_bounds__(ATH, 1)
void attn_mma(const float* __restrict__ Q, const float* __restrict__ Kn,
              const float* __restrict__ Vn, const float* __restrict__ cK,
              const float* __restrict__ cV, float* __restrict__ Out) {
  extern __shared__ unsigned sm_u[];
  float* sm_f = reinterpret_cast<float*>(sm_u);
  unsigned* Qs  = sm_u + AQS;
  unsigned* KsA = sm_u + AKS;
  unsigned* Vs  = sm_u + AVS;
  unsigned* Pu  = sm_u + APS;
  float* m_s  = sm_f + AMS;
  float* l_s  = sm_f + ALS;
  float* al_s = sm_f + AAS;
  float* smax = sm_f + ASX;   // [2][128]
  float* ssum = sm_f + ASS;   // [2][128]

  int tid = threadIdx.x;
  int h = blockIdx.y, hk = h >> 2;
  int qt = (int)gridDim.x - 1 - (int)blockIdx.x;   // heaviest CTAs first
  int q0 = qt * BQ;
  int wid = tid >> 5, lane = tid & 31;
  int gr = lane >> 2, tg = lane & 3;
  int m0 = (wid >> 1) * 16;        // warp q offset (16 rows)
  int wn = wid & 1;                // t-half (S) / d-half (PV)
  const float scale = 0.08838834764831845f;

  // ---- load Q tile (tf32, row-major, stride 132) ----
  #pragma unroll
  for (int i = 0; i < 8; i++) {
    int lin = tid + i * ATH;
    int q = lin & 127, d16 = lin >> 7;
    float4 v = *(const float4*)&Q[(size_t)(q0 + q) * DMODEL + h * HD + d16 * 4];
    unsigned* d = &Qs[q * 132 + d16 * 4];
    d[0] = f2tf(v.x); d[1] = f2tf(v.y); d[2] = f2tf(v.z); d[3] = f2tf(v.w);
  }
  if (tid < 128) { m_s[tid] = -1e30f; l_s[tid] = 0.0f; }

  // ---- load K tile 0 into Ks[0] ----
  #pragma unroll
  for (int i = 0; i < 4; i++) {
    int lin = tid + i * ATH;
    int t = lin & 63, d4 = lin >> 6;
    float4 v = *(const float4*)&cK[(size_t)t * (NHK * HD) + hk * HD + d4 * 4];
    KsA[(d4 * 4 + 0) * 68 + t] = f2tf(v.x);
    KsA[(d4 * 4 + 1) * 68 + t] = f2tf(v.y);
    KsA[(d4 * 4 + 2) * 68 + t] = f2tf(v.z);
    KsA[(d4 * 4 + 3) * 68 + t] = f2tf(v.w);
  }

  float o[8][4] = {};
  int ntiles = 34 + 2 * qt;
  int cur = 0;

  for (int tile = 0; tile < ntiles; tile++) {
    int t0 = tile * BKV;
    bool isnew = (t0 >= TCACHE);
    const float* vb = isnew ? Vn : cV;
    int tr0 = t0 & (TCACHE - 1);
    __syncthreads();   // P/Vs free; stats final; Ks[cur^1] free

    // ---- prefetch V(tile) and K(tile+1) into registers ----
    float4 vreg[4], kreg[4];
    #pragma unroll
    for (int i = 0; i < 4; i++) {
      int lin = tid + i * ATH;
      int t = lin & 63, d4 = lin >> 6;
      vreg[i] = *(const float4*)&vb[(size_t)(tr0 + t) * (NHK * HD) + hk * HD + d4 * 4];
    }
    bool havek = (tile + 1 < ntiles);
    if (havek) {
      int t1 = t0 + BKV;
      const float* kb2 = (t1 >= TCACHE) ? Kn : cK;
      int tr1 = t1 & (TCACHE - 1);
      #pragma unroll
      for (int i = 0; i < 4; i++) {
        int lin = tid + i * ATH;
        int t = lin & 63, d4 = lin >> 6;
        kreg[i] = *(const float4*)&kb2[(size_t)(tr1 + t) * (NHK * HD) + hk * HD + d4 * 4];
      }
    }

    // ---- S = Q K^T : warp tile 16q x 32t, k = 128 ----
    float s[4][4] = {};
    const unsigned* Kc = KsA + cur * 8704;
    #pragma unroll
    for (int k8 = 0; k8 < 16; k8++) {
      int kk = k8 * 8;
      unsigned af[4], bf[4][2];
      af[0] = Qs[(m0 + gr    ) * 132 + kk + tg    ];
      af[1] = Qs[(m0 + 8 + gr) * 132 + kk + tg    ];
      af[2] = Qs[(m0 + gr    ) * 132 + kk + 4 + tg];
      af[3] = Qs[(m0 + 8 + gr) * 132 + kk + 4 + tg];
      #pragma unroll
      for (int nt = 0; nt < 4; nt++) {
        int n0 = wn * 32 + nt * 8;
        bf[nt][0] = Kc[(kk + tg    ) * 68 + n0 + gr];
        bf[nt][1] = Kc[(kk + 4 + tg) * 68 + n0 + gr];
      }
      #pragma unroll
      for (int nt = 0; nt < 4; nt++)
        mma_tf32(s[nt], af, bf[nt]);
    }

    // ---- store V tile (tf32, d-major) ----
    #pragma unroll
    for (int i = 0; i < 4; i++) {
      int lin = tid + i * ATH;
      int t = lin & 63, d4 = lin >> 6;
      Vs[(d4 * 4 + 0) * 68 + t] = f2tf(vreg[i].x);
      Vs[(d4 * 4 + 1) * 68 + t] = f2tf(vreg[i].y);
      Vs[(d4 * 4 + 2) * 68 + t] = f2tf(vreg[i].z);
      Vs[(d4 * 4 + 3) * 68 + t] = f2tf(vreg[i].w);
    }

    // ---- scale + causal mask (registers) ----
    #pragma unroll
    for (int nt = 0; nt < 4; nt++) {
      int c0 = wn * 32 + nt * 8 + 2 * tg;
      #pragma unroll
      for (int half = 0; half < 2; half++) {
        int r = m0 + gr + half * 8;
        float x = s[nt][half * 2 + 0] * scale;
        float y = s[nt][half * 2 + 1] * scale;
        if (isnew) {
          if (t0 + c0     - TCACHE > q0 + r) x = -1e30f;
          if (t0 + c0 + 1 - TCACHE > q0 + r) y = -1e30f;
        }
        s[nt][half * 2 + 0] = x;
        s[nt][half * 2 + 1] = y;
      }
    }

    // ---- row max (local + shfl over tg group), publish ----
    float pm[2], mold[2];
    #pragma unroll
    for (int hf = 0; hf < 2; hf++) {
      float m1 = -1e30f;
      #pragma unroll
      for (int nt = 0; nt < 4; nt++)
        m1 = fmaxf(m1, fmaxf(s[nt][hf * 2], s[nt][hf * 2 + 1]));
      m1 = fmaxf(m1, __shfl_xor_sync(0xffffffffu, m1, 1));
      m1 = fmaxf(m1, __shfl_xor_sync(0xffffffffu, m1, 2));
      pm[hf] = m1;
      int row = m0 + hf * 8 + gr;
      mold[hf] = m_s[row];
      if (tg == 0) smax[wn * 128 + row] = m1;
    }
    __syncthreads();   // smax ready; Vs complete

    // ---- exp in registers, P as tf32, partial sums ----
    float al[2], mn[2], ps[2];
    #pragma unroll
    for (int hf = 0; hf < 2; hf++) {
      int row = m0 + hf * 8 + gr;
      float mnew = fmaxf(mold[hf], fmaxf(smax[row], smax[128 + row]));
      mn[hf] = mnew;
      al[hf] = __expf(mold[hf] - mnew);
      float sum = 0.0f;
      #pragma unroll
      for (int nt = 0; nt < 4; nt++) {
        int c0 = wn * 32 + nt * 8 + 2 * tg;
        float p0 = __expf(s[nt][hf * 2 + 0] - mnew);
        float p1 = __expf(s[nt][hf * 2 + 1] - mnew);
        sum += p0 + p1;
        uint2 w; w.x = f2tf(p0); w.y = f2tf(p1);
        *(uint2*)&Pu[row * 68 + c0] = w;
      }
      sum += __shfl_xor_sync(0xffffffffu, sum, 1);
      sum += __shfl_xor_sync(0xffffffffu, sum, 2);
      ps[hf] = sum;
      if (tg == 0) {
        ssum[wn * 128 + row] = sum;
        if (wn == 0) { al_s[row] = al[hf]; m_s[row] = mn[hf]; }
      }
    }

    // ---- store K(tile+1) into Ks[cur^1] ----
    if (havek) {
      unsigned* Kx = KsA + (cur ^ 1) * 8704;
      #pragma unroll
      for (int i = 0; i < 4; i++) {
        int lin = tid + i * ATH;
        int t = lin & 63, d4 = lin >> 6;
        Kx[(d4 * 4 + 0) * 68 + t] = f2tf(kreg[i].x);
        Kx[(d4 * 4 + 1) * 68 + t] = f2tf(kreg[i].y);
        Kx[(d4 * 4 + 2) * 68 + t] = f2tf(kreg[i].z);
        Kx[(d4 * 4 + 3) * 68 + t] = f2tf(kreg[i].w);
      }
    }
    __syncthreads();   // P, ssum, alpha, next K ready

    // ---- l update (one lane per row) ----
    if (wn == 0 && tg == 0) {
      #pragma unroll
      for (int hf = 0; hf < 2; hf++) {
        int row = m0 + hf * 8 + gr;
        l_s[row] = l_s[row] * al[hf] + ssum[row] + ssum[128 + row];
      }
    }

    // ---- rescale O, then O += P V (warp tile 16q x 64d) ----
    float alv[2];
    alv[0] = al_s[m0 + gr];
    alv[1] = al_s[m0 + 8 + gr];
    #pragma unroll
    for (int nt = 0; nt < 8; nt++) {
      o[nt][0] *= alv[0];
      o[nt][1] *= alv[0];
      o[nt][2] *= alv[1];
      o[nt][3] *= alv[1];
    }
    #pragma unroll
    for (int k8 = 0; k8 < 8; k8++) {
      int kk = k8 * 8;
      unsigned af[4], bf[8][2];
      af[0] = Pu[(m0 + gr    ) * 68 + kk + tg    ];
      af[1] = Pu[(m0 + 8 + gr) * 68 + kk + tg    ];
      af[2] = Pu[(m0 + gr    ) * 68 + kk + 4 + tg];
      af[3] = Pu[(m0 + 8 + gr) * 68 + kk + 4 + tg];
      #pragma unroll
      for (int nt = 0; nt < 8; nt++) {
        int n0 = wn * 64 + nt * 8;
        bf[nt][0] = Vs[(n0 + gr) * 68 + kk + tg    ];
        bf[nt][1] = Vs[(n0 + gr) * 68 + kk + 4 + tg];
      }
      #pragma unroll
      for (int nt = 0; nt < 8; nt++)
        mma_tf32(o[nt], af, bf[nt]);
    }
    cur ^= 1;
  }
  __syncthreads();   // final l_s visible

  // ---- epilogue: O /= l, write [q][h*128+d] ----
  float inv[2];
  inv[0] = 1.0f / l_s[m0 + gr];
  inv[1] = 1.0f / l_s[m0 + 8 + gr];
  #pragma unroll
  for (int half = 0; half < 2; half++) {
    int r = q0 + m0 + gr + half * 8;
    #pragma unroll
    for (int nt = 0; nt < 8; nt++) {
      int c = wn * 64 + nt * 8 + 2 * tg;
      float2 w;
      w.x = o[nt][half * 2 + 0] * inv[half];
      w.y = o[nt][half * 2 + 1] * inv[half];
      *(float2*)&Out[(size_t)r * DMODEL + h * HD + c] = w;
    }
  }
}

// ---------------------------------------------------------------------------
// Launch
// ---------------------------------------------------------------------------
extern "C" void kernel_launch(void* const* d_in, const int* in_sizes, int n_in,
                              void* d_out, int out_size) {
  const float* x       = (const float*)d_in[0];
  const float* rope    = (const float*)d_in[1];
  // d_in[2] = mask: unused (causality implemented exactly in-kernel)
  const float* cache_k = (const float*)d_in[3];
  const float* cache_v = (const float*)d_in[4];
  const float* wq      = (const float*)d_in[5];
  const float* wk      = (const float*)d_in[6];
  const float* wv      = (const float*)d_in[7];
  const float* wo      = (const float*)d_in[8];
  float* out = (float*)d_out;

  float *q, *k, *v, *ao;
  cudaGetSymbolAddress((void**)&q,  g_q);
  cudaGetSymbolAddress((void**)&k,  g_k);
  cudaGetSymbolAddress((void**)&v,  g_v);
  cudaGetSymbolAddress((void**)&ao, g_ao);

  cudaFuncSetAttribute(gemm_qkv, cudaFuncAttributeMaxDynamicSharedMemorySize,
                       GEMM_SMEM);
  cudaFuncSetAttribute(gemm_mma, cudaFuncAttributeMaxDynamicSharedMemorySize,
                       GEMM_SMEM);
  cudaFuncSetAttribute(attn_mma, cudaFuncAttributeMaxDynamicSharedMemorySize,
                       ATTN_SMEM_BYTES);

  // Fused QKV projection (z: 0=q w/rope, 1=k w/rope, 2=v)
  gemm_qkv<<<dim3(DMODEL / 128, S_LEN / 128, 3), 256, GEMM_SMEM>>>(
      x, wq, wk, wv, q, k, v, rope);

  // Flash attention (tf32 mma, 512 threads)
  attn_mma<<<dim3(S_LEN / BQ, NH), ATH, ATTN_SMEM_BYTES>>>(
      q, k, v, cache_k, cache_v, ao);

  // Output projection
  gemm_mma<<<dim3(DMODEL / 128, S_LEN / 128), 256, GEMM_SMEM>>>(
      ao, wo, out, DMODEL, DMODEL, (const float*)0);
}

// round 7
// speedup vs baseline: 1.0828x; 1.0828x over previous
#include <cuda_runtime.h>
#include <cuda_bf16.h>

// Problem constants
#define S_LEN  2048
#define DMODEL 4096
#define NH     32
#define NHK    8
#define HD     128
#define TCACHE 2048

// ---------------------------------------------------------------------------
// Scratch (allocation-free: __device__ globals)
// ---------------------------------------------------------------------------
__device__ float g_q [S_LEN * DMODEL];
__device__ float g_k [S_LEN * NHK * HD];
__device__ float g_v [S_LEN * NHK * HD];
__device__ float g_ao[S_LEN * DMODEL];

// ---------------------------------------------------------------------------
// Helpers
// ---------------------------------------------------------------------------
__device__ __forceinline__ unsigned f2tf(float f) {
  unsigned u;
  asm("cvt.rn.tf32.f32 %0, %1;" : "=r"(u) : "f"(f));
  return u;
}
__device__ __forceinline__ unsigned smem_u32(const void* p) {
  unsigned a;
  asm("{ .reg .u64 t; cvta.to.shared.u64 t, %1; cvt.u32.u64 %0, t; }"
      : "=r"(a) : "l"(p));
  return a;
}
__device__ __forceinline__ void cp16(unsigned dst, const void* src) {
  asm volatile("cp.async.cg.shared.global [%0], [%1], 16;"
               :: "r"(dst), "l"(src));
}
__device__ __forceinline__ void mma_tf32(float* c, const unsigned* a,
                                         const unsigned* b) {
  asm volatile(
    "mma.sync.aligned.m16n8k8.row.col.f32.tf32.tf32.f32 "
    "{%0,%1,%2,%3}, {%4,%5,%6,%7}, {%8,%9}, {%0,%1,%2,%3};"
    : "+f"(c[0]), "+f"(c[1]), "+f"(c[2]), "+f"(c[3])
    : "r"(a[0]), "r"(a[1]), "r"(a[2]), "r"(a[3]), "r"(b[0]), "r"(b[1]));
}

// ---------------------------------------------------------------------------
// Tensor-core GEMM body, 3-stage cp.async pipeline, one sync per k-iter.
// C[M,N] = A[M,K] @ B[K,N]; As stride 36, Bs stride 136 (conflict-free).
// ---------------------------------------------------------------------------
#define ASTRIDE 36
#define BSTRIDE 136
#define ABUF (128 * ASTRIDE)
#define BBUF (32 * BSTRIDE)
#define GEMM_SMEM ((3 * ABUF + 3 * BBUF) * 4)   // 107520 bytes

__device__ __forceinline__
void gemm_body(const float* __restrict__ A, const float* __restrict__ Bw,
               float* __restrict__ C, int N, int K,
               const float* __restrict__ rope, int bm, int bn, float* gsm) {
  float* AsB = gsm;                 // [3][128][36]
  float* BsB = gsm + 3 * ABUF;      // [3][32][136]
  int tid  = threadIdx.x;
  int wid  = tid >> 5, lane = tid & 31;
  int wm   = (wid >> 2) * 64;
  int wn   = (wid & 3) * 32;
  int gr   = lane >> 2;
  int tg   = lane & 3;

  int arow = tid >> 1, acol = (tid & 1) * 16;
  int brow = tid >> 3, bcol = (tid & 7) * 16;

  auto issue_copy = [&](int k0, int buf) {
    unsigned adst = smem_u32(AsB + buf * ABUF + arow * ASTRIDE + acol);
    const float* asrc = A + (size_t)(bm + arow) * K + k0 + acol;
    #pragma unroll
    for (int i = 0; i < 4; i++) cp16(adst + 16 * i, asrc + 4 * i);
    unsigned bdst = smem_u32(BsB + buf * BBUF + brow * BSTRIDE + bcol);
    const float* bsrc = Bw + (size_t)(k0 + brow) * N + bn + bcol;
    #pragma unroll
    for (int i = 0; i < 4; i++) cp16(bdst + 16 * i, bsrc + 4 * i);
    asm volatile("cp.async.commit_group;" ::: "memory");
  };

  float acc[4][4][4] = {};
  int nit = K / 32;
  issue_copy(0, 0);
  issue_copy(32, 1);

  int buf = 0;
  for (int it = 0; it < nit; it++) {
    if (it < nit - 1)
      asm volatile("cp.async.wait_group 1;" ::: "memory");
    else
      asm volatile("cp.async.wait_group 0;" ::: "memory");
    __syncthreads();
    if (it + 2 < nit) issue_copy((it + 2) * 32, (it + 2) % 3);

    const float* Ab = AsB + buf * ABUF;
    const float* Bb = BsB + buf * BBUF;
    #pragma unroll
    for (int kk = 0; kk < 32; kk += 8) {
      unsigned af[4][4], bf[4][2];
      #pragma unroll
      for (int mt = 0; mt < 4; mt++) {
        int m0 = wm + mt * 16;
        af[mt][0] = f2tf(Ab[(m0 + gr    ) * ASTRIDE + kk + tg    ]);
        af[mt][1] = f2tf(Ab[(m0 + 8 + gr) * ASTRIDE + kk + tg    ]);
        af[mt][2] = f2tf(Ab[(m0 + gr    ) * ASTRIDE + kk + 4 + tg]);
        af[mt][3] = f2tf(Ab[(m0 + 8 + gr) * ASTRIDE + kk + 4 + tg]);
      }
      #pragma unroll
      for (int nt = 0; nt < 4; nt++) {
        bf[nt][0] = f2tf(Bb[(kk + tg    ) * BSTRIDE + wn + nt * 8 + gr]);
        bf[nt][1] = f2tf(Bb[(kk + 4 + tg) * BSTRIDE + wn + nt * 8 + gr]);
      }
      #pragma unroll
      for (int mt = 0; mt < 4; mt++)
        #pragma unroll
        for (int nt = 0; nt < 4; nt++)
          mma_tf32(acc[mt][nt], af[mt], bf[nt]);
    }
    buf = (buf + 1) % 3;
  }

  #pragma unroll
  for (int mt = 0; mt < 4; mt++) {
    #pragma unroll
    for (int half = 0; half < 2; half++) {
      int m = bm + wm + mt * 16 + gr + half * 8;
      const float* rp = rope ? (rope + (size_t)m * HD) : (const float*)0;
      #pragma unroll
      for (int nt = 0; nt < 4; nt++) {
        int n = bn + wn + nt * 8 + 2 * tg;
        float x = acc[mt][nt][half * 2 + 0];
        float y = acc[mt][nt][half * 2 + 1];
        if (rp) {
          x *= rp[n & (HD - 1)];
          y *= rp[(n + 1) & (HD - 1)];
        }
        float2 v; v.x = x; v.y = y;
        *(float2*)&C[(size_t)m * N + n] = v;
      }
    }
  }
}

// Fused QKV projection, packed 1D grid (no dead CTAs):
//   blocks [0,512)   : Q  (32 n-blocks x 16 m-blocks), rope
//   blocks [512,640) : K  (8 x 16), rope
//   blocks [640,768) : V  (8 x 16)
__global__ __launch_bounds__(256, 2)
void gemm_qkv(const float* __restrict__ x,
              const float* __restrict__ wq, const float* __restrict__ wk,
              const float* __restrict__ wv,
              float* __restrict__ q, float* __restrict__ k,
              float* __restrict__ v, const float* __restrict__ rope) {
  extern __shared__ float gsm[];
  int bid = blockIdx.x;
  const float* B; float* C; int N; const float* rp; int bx, by;
  if (bid < 512) {
    B = wq; C = q; N = DMODEL; rp = rope;
    bx = bid & 31; by = bid >> 5;
  } else if (bid < 640) {
    int b2 = bid - 512;
    B = wk; C = k; N = NHK * HD; rp = rope;
    bx = b2 & 7; by = b2 >> 3;
  } else {
    int b2 = bid - 640;
    B = wv; C = v; N = NHK * HD; rp = (const float*)0;
    bx = b2 & 7; by = b2 >> 3;
  }
  gemm_body(x, B, C, N, DMODEL, rp, by * 128, bx * 128, gsm);
}

// Plain GEMM (output projection)
__global__ __launch_bounds__(256, 2)
void gemm_mma(const float* __restrict__ A, const float* __restrict__ Bw,
              float* __restrict__ C, int N, int K,
              const float* __restrict__ rope) {
  extern __shared__ float gsm[];
  gemm_body(A, Bw, C, N, K, rope, blockIdx.y * 128, blockIdx.x * 128, gsm);
}

// ---------------------------------------------------------------------------
// Tensor-core flash attention (tf32 mma), 256 threads — round-5 version
// (measured best: 1.382 ms). BQ=128, BKV=64.
// Smem (words): Qs[128][132]@0  Ks[2][128][68]@16896  Vs[128][68]@34304
//   P[128][68]@43008  m/l/al[128]@51712+  smax/ssum[2][128]@52096+
// ---------------------------------------------------------------------------
#define BQ  128
#define BKV 64
#define AQS 0
#define AKS 16896
#define AVS 34304
#define APS 43008
#define AMS 51712
#define ALS 51840
#define AAS 51968
#define ASX 52096
#define ASS 52352
#define ATTN_SMEM_BYTES (52608 * 4)

__global__ __launch_bounds__(256, 1)
void attn_mma(const float* __restrict__ Q, const float* __restrict__ Kn,
              const float* __restrict__ Vn, const float* __restrict__ cK,
              const float* __restrict__ cV, float* __restrict__ Out) {
  extern __shared__ unsigned sm_u[];
  float* sm_f = reinterpret_cast<float*>(sm_u);
  unsigned* Qs  = sm_u + AQS;
  unsigned* KsA = sm_u + AKS;
  unsigned* Vs  = sm_u + AVS;
  unsigned* Pu  = sm_u + APS;
  float* m_s  = sm_f + AMS;
  float* l_s  = sm_f + ALS;
  float* al_s = sm_f + AAS;
  float* smax = sm_f + ASX;   // [2][128]
  float* ssum = sm_f + ASS;   // [2][128]

  int tid = threadIdx.x;
  int h = blockIdx.y, hk = h >> 2;
  int q0 = blockIdx.x * BQ;
  int wid = tid >> 5, lane = tid & 31;
  int gr = lane >> 2, tg = lane & 3;
  int wm = (wid >> 1) * 32;
  int wn = wid & 1;
  const float scale = 0.08838834764831845f;

  // ---- load Q tile (tf32, row-major, stride 132) ----
  #pragma unroll
  for (int i = 0; i < 16; i++) {
    int lin = tid + i * 256;
    int q = lin & 127, d16 = lin >> 7;
    float4 v = *(const float4*)&Q[(size_t)(q0 + q) * DMODEL + h * HD + d16 * 4];
    unsigned* d = &Qs[q * 132 + d16 * 4];
    d[0] = f2tf(v.x); d[1] = f2tf(v.y); d[2] = f2tf(v.z); d[3] = f2tf(v.w);
  }
  if (tid < 128) { m_s[tid] = -1e30f; l_s[tid] = 0.0f; }

  // ---- load K tile 0 into Ks[0] ----
  #pragma unroll
  for (int i = 0; i < 8; i++) {
    int lin = tid + i * 256;
    int t = lin & 63, d4 = lin >> 6;
    float4 v = *(const float4*)&cK[(size_t)t * (NHK * HD) + hk * HD + d4 * 4];
    KsA[(d4 * 4 + 0) * 68 + t] = f2tf(v.x);
    KsA[(d4 * 4 + 1) * 68 + t] = f2tf(v.y);
    KsA[(d4 * 4 + 2) * 68 + t] = f2tf(v.z);
    KsA[(d4 * 4 + 3) * 68 + t] = f2tf(v.w);
  }

  float o[2][8][4] = {};
  int ntiles = 34 + 2 * blockIdx.x;
  int cur = 0;

  for (int tile = 0; tile < ntiles; tile++) {
    int t0 = tile * BKV;
    bool isnew = (t0 >= TCACHE);
    const float* vb = isnew ? Vn : cV;
    int tr0 = t0 & (TCACHE - 1);
    __syncthreads();   // P/Vs free; stats of prev tile final

    // ---- prefetch V(tile) and K(tile+1) into registers ----
    float4 vreg[8], kreg[8];
    #pragma unroll
    for (int i = 0; i < 8; i++) {
      int lin = tid + i * 256;
      int t = lin & 63, d4 = lin >> 6;
      vreg[i] = *(const float4*)&vb[(size_t)(tr0 + t) * (NHK * HD) + hk * HD + d4 * 4];
    }
    bool havek = (tile + 1 < ntiles);
    if (havek) {
      int t1 = t0 + BKV;
      const float* kb2 = (t1 >= TCACHE) ? Kn : cK;
      int tr1 = t1 & (TCACHE - 1);
      #pragma unroll
      for (int i = 0; i < 8; i++) {
        int lin = tid + i * 256;
        int t = lin & 63, d4 = lin >> 6;
        kreg[i] = *(const float4*)&kb2[(size_t)(tr1 + t) * (NHK * HD) + hk * HD + d4 * 4];
      }
    }

    // ---- S = Q K^T : warp tile 32q x 32t, k = 128 ----
    float s[2][4][4] = {};
    const unsigned* Kc = KsA + cur * 8704;
    #pragma unroll
    for (int k8 = 0; k8 < 16; k8++) {
      int kk = k8 * 8;
      unsigned af[2][4], bf[4][2];
      #pragma unroll
      for (int mt = 0; mt < 2; mt++) {
        int m0 = wm + mt * 16;
        af[mt][0] = Qs[(m0 + gr    ) * 132 + kk + tg    ];
        af[mt][1] = Qs[(m0 + 8 + gr) * 132 + kk + tg    ];
        af[mt][2] = Qs[(m0 + gr    ) * 132 + kk + 4 + tg];
        af[mt][3] = Qs[(m0 + 8 + gr) * 132 + kk + 4 + tg];
      }
      #pragma unroll
      for (int nt = 0; nt < 4; nt++) {
        int n0 = wn * 32 + nt * 8;
        bf[nt][0] = Kc[(kk + tg    ) * 68 + n0 + gr];
        bf[nt][1] = Kc[(kk + 4 + tg) * 68 + n0 + gr];
      }
      #pragma unroll
      for (int mt = 0; mt < 2; mt++)
        #pragma unroll
        for (int nt = 0; nt < 4; nt++)
          mma_tf32(s[mt][nt], af[mt], bf[nt]);
    }

    // ---- store V tile (tf32, d-major) ----
    #pragma unroll
    for (int i = 0; i < 8; i++) {
      int lin = tid + i * 256;
      int t = lin & 63, d4 = lin >> 6;
      Vs[(d4 * 4 + 0) * 68 + t] = f2tf(vreg[i].x);
      Vs[(d4 * 4 + 1) * 68 + t] = f2tf(vreg[i].y);
      Vs[(d4 * 4 + 2) * 68 + t] = f2tf(vreg[i].z);
      Vs[(d4 * 4 + 3) * 68 + t] = f2tf(vreg[i].w);
    }

    // ---- scale + causal mask (registers) ----
    #pragma unroll
    for (int mt = 0; mt < 2; mt++)
      #pragma unroll
      for (int nt = 0; nt < 4; nt++) {
        int c0 = wn * 32 + nt * 8 + 2 * tg;
        #pragma unroll
        for (int half = 0; half < 2; half++) {
          int r = wm + mt * 16 + gr + half * 8;
          float x = s[mt][nt][half * 2 + 0] * scale;
          float y = s[mt][nt][half * 2 + 1] * scale;
          if (isnew) {
            if (t0 + c0     - TCACHE > q0 + r) x = -1e30f;
            if (t0 + c0 + 1 - TCACHE > q0 + r) y = -1e30f;
          }
          s[mt][nt][half * 2 + 0] = x;
          s[mt][nt][half * 2 + 1] = y;
        }
      }

    // ---- row max: local, shfl over tg, publish ----
    float pm[2][2], mold[2][2];
    #pragma unroll
    for (int mt = 0; mt < 2; mt++)
      #pragma unroll
      for (int hf = 0; hf < 2; hf++) {
        float m1 = -1e30f;
        #pragma unroll
        for (int nt = 0; nt < 4; nt++)
          m1 = fmaxf(m1, fmaxf(s[mt][nt][hf * 2], s[mt][nt][hf * 2 + 1]));
        pm[mt][hf] = m1;
      }
    #pragma unroll
    for (int mt = 0; mt < 2; mt++)
      #pragma unroll
      for (int hf = 0; hf < 2; hf++) {
        pm[mt][hf] = fmaxf(pm[mt][hf], __shfl_xor_sync(0xffffffffu, pm[mt][hf], 1));
        pm[mt][hf] = fmaxf(pm[mt][hf], __shfl_xor_sync(0xffffffffu, pm[mt][hf], 2));
        int row = wm + mt * 16 + hf * 8 + gr;
        mold[mt][hf] = m_s[row];
        if (tg == 0) smax[wn * 128 + row] = pm[mt][hf];
      }
    __syncthreads();   // smax ready; Vs complete

    // ---- exp in registers, P as tf32, partial sums ----
    float al[2][2], mn[2][2], ps[2][2];
    #pragma unroll
    for (int mt = 0; mt < 2; mt++)
      #pragma unroll
      for (int hf = 0; hf < 2; hf++) {
        int row = wm + mt * 16 + hf * 8 + gr;
        float mnew = fmaxf(mold[mt][hf],
                           fmaxf(smax[row], smax[128 + row]));
        mn[mt][hf] = mnew;
        al[mt][hf] = __expf(mold[mt][hf] - mnew);
        float sum = 0.0f;
        #pragma unroll
        for (int nt = 0; nt < 4; nt++) {
          int c0 = wn * 32 + nt * 8 + 2 * tg;
          float p0 = __expf(s[mt][nt][hf * 2 + 0] - mnew);
          float p1 = __expf(s[mt][nt][hf * 2 + 1] - mnew);
          sum += p0 + p1;
          uint2 w; w.x = f2tf(p0); w.y = f2tf(p1);
          *(uint2*)&Pu[row * 68 + c0] = w;
        }
        ps[mt][hf] = sum;
      }
    #pragma unroll
    for (int mt = 0; mt < 2; mt++)
      #pragma unroll
      for (int hf = 0; hf < 2; hf++) {
        ps[mt][hf] += __shfl_xor_sync(0xffffffffu, ps[mt][hf], 1);
        ps[mt][hf] += __shfl_xor_sync(0xffffffffu, ps[mt][hf], 2);
        int row = wm + mt * 16 + hf * 8 + gr;
        if (tg == 0) {
          ssum[wn * 128 + row] = ps[mt][hf];
          if (wn == 0) { al_s[row] = al[mt][hf]; m_s[row] = mn[mt][hf]; }
        }
      }

    // ---- store K(tile+1) into Ks[cur^1] ----
    if (havek) {
      unsigned* Kx = KsA + (cur ^ 1) * 8704;
      #pragma unroll
      for (int i = 0; i < 8; i++) {
        int lin = tid + i * 256;
        int t = lin & 63, d4 = lin >> 6;
        Kx[(d4 * 4 + 0) * 68 + t] = f2tf(kreg[i].x);
        Kx[(d4 * 4 + 1) * 68 + t] = f2tf(kreg[i].y);
        Kx[(d4 * 4 + 2) * 68 + t] = f2tf(kreg[i].z);
        Kx[(d4 * 4 + 3) * 68 + t] = f2tf(kreg[i].w);
      }
    }
    __syncthreads();   // P, ssum, alpha, next K ready

    // ---- l update (one lane per row) ----
    if (wn == 0 && tg == 0) {
      #pragma unroll
      for (int mt = 0; mt < 2; mt++)
        #pragma unroll
        for (int hf = 0; hf < 2; hf++) {
          int row = wm + mt * 16 + hf * 8 + gr;
          l_s[row] = l_s[row] * al[mt][hf] + ssum[row] + ssum[128 + row];
        }
    }

    // ---- rescale O by alpha, then O += P V ----
    float alv[2][2];
    alv[0][0] = al_s[wm + gr];
    alv[0][1] = al_s[wm + 8 + gr];
    alv[1][0] = al_s[wm + 16 + gr];
    alv[1][1] = al_s[wm + 24 + gr];
    #pragma unroll
    for (int mt = 0; mt < 2; mt++)
      #pragma unroll
      for (int nt = 0; nt < 8; nt++) {
        o[mt][nt][0] *= alv[mt][0];
        o[mt][nt][1] *= alv[mt][0];
        o[mt][nt][2] *= alv[mt][1];
        o[mt][nt][3] *= alv[mt][1];
      }
    #pragma unroll
    for (int k8 = 0; k8 < 8; k8++) {
      int kk = k8 * 8;
      unsigned af[2][4], bf[8][2];
      #pragma unroll
      for (int mt = 0; mt < 2; mt++) {
        int m0 = wm + mt * 16;
        af[mt][0] = Pu[(m0 + gr    ) * 68 + kk + tg    ];
        af[mt][1] = Pu[(m0 + 8 + gr) * 68 + kk + tg    ];
        af[mt][2] = Pu[(m0 + gr    ) * 68 + kk + 4 + tg];
        af[mt][3] = Pu[(m0 + 8 + gr) * 68 + kk + 4 + tg];
      }
      #pragma unroll
      for (int nt = 0; nt < 8; nt++) {
        int n0 = wn * 64 + nt * 8;
        bf[nt][0] = Vs[(n0 + gr) * 68 + kk + tg    ];
        bf[nt][1] = Vs[(n0 + gr) * 68 + kk + 4 + tg];
      }
      #pragma unroll
      for (int mt = 0; mt < 2; mt++)
        #pragma unroll
        for (int nt = 0; nt < 8; nt++)
          mma_tf32(o[mt][nt], af[mt], bf[nt]);
    }
    cur ^= 1;
  }
  __syncthreads();   // final l_s writes visible

  // ---- epilogue: O /= l, write [q][h*128+d] ----
  float inv[2][2];
  inv[0][0] = 1.0f / l_s[wm + gr];
  inv[0][1] = 1.0f / l_s[wm + 8 + gr];
  inv[1][0] = 1.0f / l_s[wm + 16 + gr];
  inv[1][1] = 1.0f / l_s[wm + 24 + gr];
  #pragma unroll
  for (int mt = 0; mt < 2; mt++)
    #pragma unroll
    for (int half = 0; half < 2; half++) {
      int r = q0 + wm + mt * 16 + gr + half * 8;
      #pragma unroll
      for (int nt = 0; nt < 8; nt++) {
        int c = wn * 64 + nt * 8 + 2 * tg;
        float2 w;
        w.x = o[mt][nt][half * 2 + 0] * inv[mt][half];
        w.y = o[mt][nt][half * 2 + 1] * inv[mt][half];
        *(float2*)&Out[(size_t)r * DMODEL + h * HD + c] = w;
      }
    }
}

// ---------------------------------------------------------------------------
// Launch
// ---------------------------------------------------------------------------
extern "C" void kernel_launch(void* const* d_in, const int* in_sizes, int n_in,
                              void* d_out, int out_size) {
  const float* x       = (const float*)d_in[0];
  const float* rope    = (const float*)d_in[1];
  // d_in[2] = mask: unused (causality implemented exactly in-kernel)
  const float* cache_k = (const float*)d_in[3];
  const float* cache_v = (const float*)d_in[4];
  const float* wq      = (const float*)d_in[5];
  const float* wk      = (const float*)d_in[6];
  const float* wv      = (const float*)d_in[7];
  const float* wo      = (const float*)d_in[8];
  float* out = (float*)d_out;

  float *q, *k, *v, *ao;
  cudaGetSymbolAddress((void**)&q,  g_q);
  cudaGetSymbolAddress((void**)&k,  g_k);
  cudaGetSymbolAddress((void**)&v,  g_v);
  cudaGetSymbolAddress((void**)&ao, g_ao);

  cudaFuncSetAttribute(gemm_qkv, cudaFuncAttributeMaxDynamicSharedMemorySize,
                       GEMM_SMEM);
  cudaFuncSetAttribute(gemm_mma, cudaFuncAttributeMaxDynamicSharedMemorySize,
                       GEMM_SMEM);
  cudaFuncSetAttribute(attn_mma, cudaFuncAttributeMaxDynamicSharedMemorySize,
                       ATTN_SMEM_BYTES);

  // Fused QKV projection (packed 1D grid: 512 Q + 128 K + 128 V = 768 CTAs)
  gemm_qkv<<<768, 256, GEMM_SMEM>>>(x, wq, wk, wv, q, k, v, rope);

  // Flash attention (tf32 mma, 256 threads — round-5 best)
  attn_mma<<<dim3(S_LEN / BQ, NH), 256, ATTN_SMEM_BYTES>>>(
      q, k, v, cache_k, cache_v, ao);

  // Output projection
  gemm_mma<<<dim3(DMODEL / 128, S_LEN / 128), 256, GEMM_SMEM>>>(
      ao, wo, out, DMODEL, DMODEL, (const float*)0);
}

// round 8
// speedup vs baseline: 1.0985x; 1.0145x over previous
#include <cuda_runtime.h>
#include <cuda_bf16.h>

// Problem constants
#define S_LEN  2048
#define DMODEL 4096
#define NH     32
#define NHK    8
#define HD     128
#define TCACHE 2048

// ---------------------------------------------------------------------------
// Scratch (allocation-free: __device__ globals)
// ---------------------------------------------------------------------------
__device__ float    g_q [S_LEN * DMODEL];
__device__ float    g_k [S_LEN * NHK * HD];
__device__ float    g_v [S_LEN * NHK * HD];
__device__ float    g_ao[S_LEN * DMODEL];             // tf32 bits (from attn)
__device__ unsigned g_xc [S_LEN * DMODEL];            // x   as tf32
__device__ unsigned g_wqc[DMODEL * DMODEL];           // wq  as tf32
__device__ unsigned g_wkc[DMODEL * NHK * HD];         // wk  as tf32
__device__ unsigned g_wvc[DMODEL * NHK * HD];         // wv  as tf32
__device__ unsigned g_woc[DMODEL * DMODEL];           // wo  as tf32

// ---------------------------------------------------------------------------
// Helpers
// ---------------------------------------------------------------------------
__device__ __forceinline__ unsigned f2tf(float f) {
  unsigned u;
  asm("cvt.rn.tf32.f32 %0, %1;" : "=r"(u) : "f"(f));
  return u;
}
__device__ __forceinline__ unsigned smem_u32(const void* p) {
  unsigned a;
  asm("{ .reg .u64 t; cvta.to.shared.u64 t, %1; cvt.u32.u64 %0, t; }"
      : "=r"(a) : "l"(p));
  return a;
}
__device__ __forceinline__ void cp16(unsigned dst, const void* src) {
  asm volatile("cp.async.cg.shared.global [%0], [%1], 16;"
               :: "r"(dst), "l"(src));
}
__device__ __forceinline__ void mma_tf32(float* c, const unsigned* a,
                                         const unsigned* b) {
  asm volatile(
    "mma.sync.aligned.m16n8k8.row.col.f32.tf32.tf32.f32 "
    "{%0,%1,%2,%3}, {%4,%5,%6,%7}, {%8,%9}, {%0,%1,%2,%3};"
    : "+f"(c[0]), "+f"(c[1]), "+f"(c[2]), "+f"(c[3])
    : "r"(a[0]), "r"(a[1]), "r"(a[2]), "r"(a[3]), "r"(b[0]), "r"(b[1]));
}

// ---------------------------------------------------------------------------
// Elementwise fp32 -> tf32 bit-pattern conversion (vectorized, 4 elem/thread)
// ---------------------------------------------------------------------------
__global__ __launch_bounds__(256)
void conv_tf32(const float* __restrict__ in, unsigned* __restrict__ out) {
  size_t i = ((size_t)blockIdx.x * 256 + threadIdx.x) * 4;
  float4 v = *(const float4*)(in + i);
  uint4 o;
  o.x = f2tf(v.x); o.y = f2tf(v.y); o.z = f2tf(v.z); o.w = f2tf(v.w);
  *(uint4*)(out + i) = o;
}

// ---------------------------------------------------------------------------
// Tensor-core GEMM body: operands are PRE-CONVERTED tf32 (no cvt in mainloop).
// 3-stage cp.async pipeline, one sync per k-iter.
// C[M,N] = A[M,K] @ B[K,N]; As stride 36, Bs stride 136 (conflict-free).
// ---------------------------------------------------------------------------
#define ASTRIDE 36
#define BSTRIDE 136
#define ABUF (128 * ASTRIDE)
#define BBUF (32 * BSTRIDE)
#define GEMM_SMEM ((3 * ABUF + 3 * BBUF) * 4)   // 107520 bytes

__device__ __forceinline__
void gemm_body(const unsigned* __restrict__ A, const unsigned* __restrict__ Bw,
               float* __restrict__ C, int N, int K,
               const float* __restrict__ rope, int bm, int bn, unsigned* gsm) {
  unsigned* AsB = gsm;                 // [3][128][36]
  unsigned* BsB = gsm + 3 * ABUF;      // [3][32][136]
  int tid  = threadIdx.x;
  int wid  = tid >> 5, lane = tid & 31;
  int wm   = (wid >> 2) * 64;
  int wn   = (wid & 3) * 32;
  int gr   = lane >> 2;
  int tg   = lane & 3;

  int arow = tid >> 1, acol = (tid & 1) * 16;
  int brow = tid >> 3, bcol = (tid & 7) * 16;

  auto issue_copy = [&](int k0, int buf) {
    unsigned adst = smem_u32(AsB + buf * ABUF + arow * ASTRIDE + acol);
    const unsigned* asrc = A + (size_t)(bm + arow) * K + k0 + acol;
    #pragma unroll
    for (int i = 0; i < 4; i++) cp16(adst + 16 * i, asrc + 4 * i);
    unsigned bdst = smem_u32(BsB + buf * BBUF + brow * BSTRIDE + bcol);
    const unsigned* bsrc = Bw + (size_t)(k0 + brow) * N + bn + bcol;
    #pragma unroll
    for (int i = 0; i < 4; i++) cp16(bdst + 16 * i, bsrc + 4 * i);
    asm volatile("cp.async.commit_group;" ::: "memory");
  };

  float acc[4][4][4] = {};
  int nit = K / 32;
  issue_copy(0, 0);
  issue_copy(32, 1);

  int buf = 0;
  for (int it = 0; it < nit; it++) {
    if (it < nit - 1)
      asm volatile("cp.async.wait_group 1;" ::: "memory");
    else
      asm volatile("cp.async.wait_group 0;" ::: "memory");
    __syncthreads();
    if (it + 2 < nit) issue_copy((it + 2) * 32, (it + 2) % 3);

    const unsigned* Ab = AsB + buf * ABUF;
    const unsigned* Bb = BsB + buf * BBUF;
    #pragma unroll
    for (int kk = 0; kk < 32; kk += 8) {
      unsigned af[4][4], bf[4][2];
      #pragma unroll
      for (int mt = 0; mt < 4; mt++) {
        int m0 = wm + mt * 16;
        af[mt][0] = Ab[(m0 + gr    ) * ASTRIDE + kk + tg    ];
        af[mt][1] = Ab[(m0 + 8 + gr) * ASTRIDE + kk + tg    ];
        af[mt][2] = Ab[(m0 + gr    ) * ASTRIDE + kk + 4 + tg];
        af[mt][3] = Ab[(m0 + 8 + gr) * ASTRIDE + kk + 4 + tg];
      }
      #pragma unroll
      for (int nt = 0; nt < 4; nt++) {
        bf[nt][0] = Bb[(kk + tg    ) * BSTRIDE + wn + nt * 8 + gr];
        bf[nt][1] = Bb[(kk + 4 + tg) * BSTRIDE + wn + nt * 8 + gr];
      }
      #pragma unroll
      for (int mt = 0; mt < 4; mt++)
        #pragma unroll
        for (int nt = 0; nt < 4; nt++)
          mma_tf32(acc[mt][nt], af[mt], bf[nt]);
    }
    buf = (buf + 1) % 3;
  }

  #pragma unroll
  for (int mt = 0; mt < 4; mt++) {
    #pragma unroll
    for (int half = 0; half < 2; half++) {
      int m = bm + wm + mt * 16 + gr + half * 8;
      const float* rp = rope ? (rope + (size_t)m * HD) : (const float*)0;
      #pragma unroll
      for (int nt = 0; nt < 4; nt++) {
        int n = bn + wn + nt * 8 + 2 * tg;
        float x = acc[mt][nt][half * 2 + 0];
        float y = acc[mt][nt][half * 2 + 1];
        if (rp) {
          x *= rp[n & (HD - 1)];
          y *= rp[(n + 1) & (HD - 1)];
        }
        float2 v; v.x = x; v.y = y;
        *(float2*)&C[(size_t)m * N + n] = v;
      }
    }
  }
}

// Fused QKV projection, packed 1D grid (no dead CTAs):
//   blocks [0,512)   : Q  (32 n-blocks x 16 m-blocks), rope
//   blocks [512,640) : K  (8 x 16), rope
//   blocks [640,768) : V  (8 x 16)
__global__ __launch_bounds__(256, 2)
void gemm_qkv(const unsigned* __restrict__ x,
              const unsigned* __restrict__ wq, const unsigned* __restrict__ wk,
              const unsigned* __restrict__ wv,
              float* __restrict__ q, float* __restrict__ k,
              float* __restrict__ v, const float* __restrict__ rope) {
  extern __shared__ unsigned gsm[];
  int bid = blockIdx.x;
  const unsigned* B; float* C; int N; const float* rp; int bx, by;
  if (bid < 512) {
    B = wq; C = q; N = DMODEL; rp = rope;
    bx = bid & 31; by = bid >> 5;
  } else if (bid < 640) {
    int b2 = bid - 512;
    B = wk; C = k; N = NHK * HD; rp = rope;
    bx = b2 & 7; by = b2 >> 3;
  } else {
    int b2 = bid - 640;
    B = wv; C = v; N = NHK * HD; rp = (const float*)0;
    bx = b2 & 7; by = b2 >> 3;
  }
  gemm_body(x, B, C, N, DMODEL, rp, by * 128, bx * 128, gsm);
}

// Plain GEMM (output projection)
__global__ __launch_bounds__(256, 2)
void gemm_mma(const unsigned* __restrict__ A, const unsigned* __restrict__ Bw,
              float* __restrict__ C, int N, int K,
              const float* __restrict__ rope) {
  extern __shared__ unsigned gsm[];
  gemm_body(A, Bw, C, N, K, rope, blockIdx.y * 128, blockIdx.x * 128, gsm);
}

// ---------------------------------------------------------------------------
// Tensor-core flash attention (tf32 mma), 256 threads — round-5/7 version
// (measured 1.382 ms). Epilogue now stores tf32 bit-patterns (feeds wo GEMM).
// ---------------------------------------------------------------------------
#define BQ  128
#define BKV 64
#define AQS 0
#define AKS 16896
#define AVS 34304
#define APS 43008
#define AMS 51712
#define ALS 51840
#define AAS 51968
#define ASX 52096
#define ASS 52352
#define ATTN_SMEM_BYTES (52608 * 4)

__global__ __launch_bounds__(256, 1)
void attn_mma(const float* __restrict__ Q, const float* __restrict__ Kn,
              const float* __restrict__ Vn, const float* __restrict__ cK,
              const float* __restrict__ cV, float* __restrict__ Out) {
  extern __shared__ unsigned sm_u[];
  float* sm_f = reinterpret_cast<float*>(sm_u);
  unsigned* Qs  = sm_u + AQS;
  unsigned* KsA = sm_u + AKS;
  unsigned* Vs  = sm_u + AVS;
  unsigned* Pu  = sm_u + APS;
  float* m_s  = sm_f + AMS;
  float* l_s  = sm_f + ALS;
  float* al_s = sm_f + AAS;
  float* smax = sm_f + ASX;   // [2][128]
  float* ssum = sm_f + ASS;   // [2][128]

  int tid = threadIdx.x;
  int h = blockIdx.y, hk = h >> 2;
  int q0 = blockIdx.x * BQ;
  int wid = tid >> 5, lane = tid & 31;
  int gr = lane >> 2, tg = lane & 3;
  int wm = (wid >> 1) * 32;
  int wn = wid & 1;
  const float scale = 0.08838834764831845f;

  // ---- load Q tile (tf32, row-major, stride 132) ----
  #pragma unroll
  for (int i = 0; i < 16; i++) {
    int lin = tid + i * 256;
    int q = lin & 127, d16 = lin >> 7;
    float4 v = *(const float4*)&Q[(size_t)(q0 + q) * DMODEL + h * HD + d16 * 4];
    unsigned* d = &Qs[q * 132 + d16 * 4];
    d[0] = f2tf(v.x); d[1] = f2tf(v.y); d[2] = f2tf(v.z); d[3] = f2tf(v.w);
  }
  if (tid < 128) { m_s[tid] = -1e30f; l_s[tid] = 0.0f; }

  // ---- load K tile 0 into Ks[0] ----
  #pragma unroll
  for (int i = 0; i < 8; i++) {
    int lin = tid + i * 256;
    int t = lin & 63, d4 = lin >> 6;
    float4 v = *(const float4*)&cK[(size_t)t * (NHK * HD) + hk * HD + d4 * 4];
    KsA[(d4 * 4 + 0) * 68 + t] = f2tf(v.x);
    KsA[(d4 * 4 + 1) * 68 + t] = f2tf(v.y);
    KsA[(d4 * 4 + 2) * 68 + t] = f2tf(v.z);
    KsA[(d4 * 4 + 3) * 68 + t] = f2tf(v.w);
  }

  float o[2][8][4] = {};
  int ntiles = 34 + 2 * blockIdx.x;
  int cur = 0;

  for (int tile = 0; tile < ntiles; tile++) {
    int t0 = tile * BKV;
    bool isnew = (t0 >= TCACHE);
    const float* vb = isnew ? Vn : cV;
    int tr0 = t0 & (TCACHE - 1);
    __syncthreads();   // P/Vs free; stats of prev tile final

    // ---- prefetch V(tile) and K(tile+1) into registers ----
    float4 vreg[8], kreg[8];
    #pragma unroll
    for (int i = 0; i < 8; i++) {
      int lin = tid + i * 256;
      int t = lin & 63, d4 = lin >> 6;
      vreg[i] = *(const float4*)&vb[(size_t)(tr0 + t) * (NHK * HD) + hk * HD + d4 * 4];
    }
    bool havek = (tile + 1 < ntiles);
    if (havek) {
      int t1 = t0 + BKV;
      const float* kb2 = (t1 >= TCACHE) ? Kn : cK;
      int tr1 = t1 & (TCACHE - 1);
      #pragma unroll
      for (int i = 0; i < 8; i++) {
        int lin = tid + i * 256;
        int t = lin & 63, d4 = lin >> 6;
        kreg[i] = *(const float4*)&kb2[(size_t)(tr1 + t) * (NHK * HD) + hk * HD + d4 * 4];
      }
    }

    // ---- S = Q K^T : warp tile 32q x 32t, k = 128 ----
    float s[2][4][4] = {};
    const unsigned* Kc = KsA + cur * 8704;
    #pragma unroll
    for (int k8 = 0; k8 < 16; k8++) {
      int kk = k8 * 8;
      unsigned af[2][4], bf[4][2];
      #pragma unroll
      for (int mt = 0; mt < 2; mt++) {
        int m0 = wm + mt * 16;
        af[mt][0] = Qs[(m0 + gr    ) * 132 + kk + tg    ];
        af[mt][1] = Qs[(m0 + 8 + gr) * 132 + kk + tg    ];
        af[mt][2] = Qs[(m0 + gr    ) * 132 + kk + 4 + tg];
        af[mt][3] = Qs[(m0 + 8 + gr) * 132 + kk + 4 + tg];
      }
      #pragma unroll
      for (int nt = 0; nt < 4; nt++) {
        int n0 = wn * 32 + nt * 8;
        bf[nt][0] = Kc[(kk + tg    ) * 68 + n0 + gr];
        bf[nt][1] = Kc[(kk + 4 + tg) * 68 + n0 + gr];
      }
      #pragma unroll
      for (int mt = 0; mt < 2; mt++)
        #pragma unroll
        for (int nt = 0; nt < 4; nt++)
          mma_tf32(s[mt][nt], af[mt], bf[nt]);
    }

    // ---- store V tile (tf32, d-major) ----
    #pragma unroll
    for (int i = 0; i < 8; i++) {
      int lin = tid + i * 256;
      int t = lin & 63, d4 = lin >> 6;
      Vs[(d4 * 4 + 0) * 68 + t] = f2tf(vreg[i].x);
      Vs[(d4 * 4 + 1) * 68 + t] = f2tf(vreg[i].y);
      Vs[(d4 * 4 + 2) * 68 + t] = f2tf(vreg[i].z);
      Vs[(d4 * 4 + 3) * 68 + t] = f2tf(vreg[i].w);
    }

    // ---- scale + causal mask (registers) ----
    #pragma unroll
    for (int mt = 0; mt < 2; mt++)
      #pragma unroll
      for (int nt = 0; nt < 4; nt++) {
        int c0 = wn * 32 + nt * 8 + 2 * tg;
        #pragma unroll
        for (int half = 0; half < 2; half++) {
          int r = wm + mt * 16 + gr + half * 8;
          float x = s[mt][nt][half * 2 + 0] * scale;
          float y = s[mt][nt][half * 2 + 1] * scale;
          if (isnew) {
            if (t0 + c0     - TCACHE > q0 + r) x = -1e30f;
            if (t0 + c0 + 1 - TCACHE > q0 + r) y = -1e30f;
          }
          s[mt][nt][half * 2 + 0] = x;
          s[mt][nt][half * 2 + 1] = y;
        }
      }

    // ---- row max: local, shfl over tg, publish ----
    float pm[2][2], mold[2][2];
    #pragma unroll
    for (int mt = 0; mt < 2; mt++)
      #pragma unroll
      for (int hf = 0; hf < 2; hf++) {
        float m1 = -1e30f;
        #pragma unroll
        for (int nt = 0; nt < 4; nt++)
          m1 = fmaxf(m1, fmaxf(s[mt][nt][hf * 2], s[mt][nt][hf * 2 + 1]));
        pm[mt][hf] = m1;
      }
    #pragma unroll
    for (int mt = 0; mt < 2; mt++)
      #pragma unroll
      for (int hf = 0; hf < 2; hf++) {
        pm[mt][hf] = fmaxf(pm[mt][hf], __shfl_xor_sync(0xffffffffu, pm[mt][hf], 1));
        pm[mt][hf] = fmaxf(pm[mt][hf], __shfl_xor_sync(0xffffffffu, pm[mt][hf], 2));
        int row = wm + mt * 16 + hf * 8 + gr;
        mold[mt][hf] = m_s[row];
        if (tg == 0) smax[wn * 128 + row] = pm[mt][hf];
      }
    __syncthreads();   // smax ready; Vs complete

    // ---- exp in registers, P as tf32, partial sums ----
    float al[2][2], mn[2][2], ps[2][2];
    #pragma unroll
    for (int mt = 0; mt < 2; mt++)
      #pragma unroll
      for (int hf = 0; hf < 2; hf++) {
        int row = wm + mt * 16 + hf * 8 + gr;
        float mnew = fmaxf(mold[mt][hf],
                           fmaxf(smax[row], smax[128 + row]));
        mn[mt][hf] = mnew;
        al[mt][hf] = __expf(mold[mt][hf] - mnew);
        float sum = 0.0f;
        #pragma unroll
        for (int nt = 0; nt < 4; nt++) {
          int c0 = wn * 32 + nt * 8 + 2 * tg;
          float p0 = __expf(s[mt][nt][hf * 2 + 0] - mnew);
          float p1 = __expf(s[mt][nt][hf * 2 + 1] - mnew);
          sum += p0 + p1;
          uint2 w; w.x = f2tf(p0); w.y = f2tf(p1);
          *(uint2*)&Pu[row * 68 + c0] = w;
        }
        ps[mt][hf] = sum;
      }
    #pragma unroll
    for (int mt = 0; mt < 2; mt++)
      #pragma unroll
      for (int hf = 0; hf < 2; hf++) {
        ps[mt][hf] += __shfl_xor_sync(0xffffffffu, ps[mt][hf], 1);
        ps[mt][hf] += __shfl_xor_sync(0xffffffffu, ps[mt][hf], 2);
        int row = wm + mt * 16 + hf * 8 + gr;
        if (tg == 0) {
          ssum[wn * 128 + row] = ps[mt][hf];
          if (wn == 0) { al_s[row] = al[mt][hf]; m_s[row] = mn[mt][hf]; }
        }
      }

    // ---- store K(tile+1) into Ks[cur^1] ----
    if (havek) {
      unsigned* Kx = KsA + (cur ^ 1) * 8704;
      #pragma unroll
      for (int i = 0; i < 8; i++) {
        int lin = tid + i * 256;
        int t = lin & 63, d4 = lin >> 6;
        Kx[(d4 * 4 + 0) * 68 + t] = f2tf(kreg[i].x);
        Kx[(d4 * 4 + 1) * 68 + t] = f2tf(kreg[i].y);
        Kx[(d4 * 4 + 2) * 68 + t] = f2tf(kreg[i].z);
        Kx[(d4 * 4 + 3) * 68 + t] = f2tf(kreg[i].w);
      }
    }
    __syncthreads();   // P, ssum, alpha, next K ready

    // ---- l update (one lane per row) ----
    if (wn == 0 && tg == 0) {
      #pragma unroll
      for (int mt = 0; mt < 2; mt++)
        #pragma unroll
        for (int hf = 0; hf < 2; hf++) {
          int row = wm + mt * 16 + hf * 8 + gr;
          l_s[row] = l_s[row] * al[mt][hf] + ssum[row] + ssum[128 + row];
        }
    }

    // ---- rescale O by alpha, then O += P V ----
    float alv[2][2];
    alv[0][0] = al_s[wm + gr];
    alv[0][1] = al_s[wm + 8 + gr];
    alv[1][0] = al_s[wm + 16 + gr];
    alv[1][1] = al_s[wm + 24 + gr];
    #pragma unroll
    for (int mt = 0; mt < 2; mt++)
      #pragma unroll
      for (int nt = 0; nt < 8; nt++) {
        o[mt][nt][0] *= alv[mt][0];
        o[mt][nt][1] *= alv[mt][0];
        o[mt][nt][2] *= alv[mt][1];
        o[mt][nt][3] *= alv[mt][1];
      }
    #pragma unroll
    for (int k8 = 0; k8 < 8; k8++) {
      int kk = k8 * 8;
      unsigned af[2][4], bf[8][2];
      #pragma unroll
      for (int mt = 0; mt < 2; mt++) {
        int m0 = wm + mt * 16;
        af[mt][0] = Pu[(m0 + gr    ) * 68 + kk + tg    ];
        af[mt][1] = Pu[(m0 + 8 + gr) * 68 + kk + tg    ];
        af[mt][2] = Pu[(m0 + gr    ) * 68 + kk + 4 + tg];
        af[mt][3] = Pu[(m0 + 8 + gr) * 68 + kk + 4 + tg];
      }
      #pragma unroll
      for (int nt = 0; nt < 8; nt++) {
        int n0 = wn * 64 + nt * 8;
        bf[nt][0] = Vs[(n0 + gr) * 68 + kk + tg    ];
        bf[nt][1] = Vs[(n0 + gr) * 68 + kk + 4 + tg];
      }
      #pragma unroll
      for (int mt = 0; mt < 2; mt++)
        #pragma unroll
        for (int nt = 0; nt < 8; nt++)
          mma_tf32(o[mt][nt], af[mt], bf[nt]);
    }
    cur ^= 1;
  }
  __syncthreads();   // final l_s writes visible

  // ---- epilogue: O /= l, write tf32 bits [q][h*128+d] (feeds wo GEMM) ----
  float inv[2][2];
  inv[0][0] = 1.0f / l_s[wm + gr];
  inv[0][1] = 1.0f / l_s[wm + 8 + gr];
  inv[1][0] = 1.0f / l_s[wm + 16 + gr];
  inv[1][1] = 1.0f / l_s[wm + 24 + gr];
  #pragma unroll
  for (int mt = 0; mt < 2; mt++)
    #pragma unroll
    for (int half = 0; half < 2; half++) {
      int r = q0 + wm + mt * 16 + gr + half * 8;
      #pragma unroll
      for (int nt = 0; nt < 8; nt++) {
        int c = wn * 64 + nt * 8 + 2 * tg;
        float2 w;
        w.x = __uint_as_float(f2tf(o[mt][nt][half * 2 + 0] * inv[mt][half]));
        w.y = __uint_as_float(f2tf(o[mt][nt][half * 2 + 1] * inv[mt][half]));
        *(float2*)&Out[(size_t)r * DMODEL + h * HD + c] = w;
      }
    }
}

// ---------------------------------------------------------------------------
// Launch
// ---------------------------------------------------------------------------
extern "C" void kernel_launch(void* const* d_in, const int* in_sizes, int n_in,
                              void* d_out, int out_size) {
  const float* x       = (const float*)d_in[0];
  const float* rope    = (const float*)d_in[1];
  // d_in[2] = mask: unused (causality implemented exactly in-kernel)
  const float* cache_k = (const float*)d_in[3];
  const float* cache_v = (const float*)d_in[4];
  const float* wq      = (const float*)d_in[5];
  const float* wk      = (const float*)d_in[6];
  const float* wv      = (const float*)d_in[7];
  const float* wo      = (const float*)d_in[8];
  float* out = (float*)d_out;

  float *q, *k, *v, *ao;
  unsigned *xc, *wqc, *wkc, *wvc, *woc;
  cudaGetSymbolAddress((void**)&q,   g_q);
  cudaGetSymbolAddress((void**)&k,   g_k);
  cudaGetSymbolAddress((void**)&v,   g_v);
  cudaGetSymbolAddress((void**)&ao,  g_ao);
  cudaGetSymbolAddress((void**)&xc,  g_xc);
  cudaGetSymbolAddress((void**)&wqc, g_wqc);
  cudaGetSymbolAddress((void**)&wkc, g_wkc);
  cudaGetSymbolAddress((void**)&wvc, g_wvc);
  cudaGetSymbolAddress((void**)&woc, g_woc);

  cudaFuncSetAttribute(gemm_qkv, cudaFuncAttributeMaxDynamicSharedMemorySize,
                       GEMM_SMEM);
  cudaFuncSetAttribute(gemm_mma, cudaFuncAttributeMaxDynamicSharedMemorySize,
                       GEMM_SMEM);
  cudaFuncSetAttribute(attn_mma, cudaFuncAttributeMaxDynamicSharedMemorySize,
                       ATTN_SMEM_BYTES);

  // Pre-convert operands to tf32 (removes cvt from GEMM mainloops)
  conv_tf32<<<(S_LEN * DMODEL) / 1024, 256>>>(x, xc);
  conv_tf32<<<(DMODEL * DMODEL) / 1024, 256>>>(wq, wqc);
  conv_tf32<<<(DMODEL * NHK * HD) / 1024, 256>>>(wk, wkc);
  conv_tf32<<<(DMODEL * NHK * HD) / 1024, 256>>>(wv, wvc);
  conv_tf32<<<(DMODEL * DMODEL) / 1024, 256>>>(wo, woc);

  // Fused QKV projection (packed 1D grid: 512 Q + 128 K + 128 V = 768 CTAs)
  gemm_qkv<<<768, 256, GEMM_SMEM>>>(xc, wqc, wkc, wvc, q, k, v, rope);

  // Flash attention (tf32 mma, 256 threads)
  attn_mma<<<dim3(S_LEN / BQ, NH), 256, ATTN_SMEM_BYTES>>>(
      q, k, v, cache_k, cache_v, ao);

  // Output projection (ao already tf32 bits from attn epilogue)
  gemm_mma<<<dim3(DMODEL / 128, S_LEN / 128), 256, GEMM_SMEM>>>(
      (const unsigned*)ao, woc, out, DMODEL, DMODEL, (const float*)0);
}